// round 16
// baseline (speedup 1.0000x reference)
#include <cuda_runtime.h>
#include <cuda_fp16.h>
#include <math.h>
#include <stdint.h>

#define GN 4096
#define UN 100000
#define IN_ 8192
#define FN 128
#define MN 8192
#define NNZ_RUI 500000
#define NNZ_RGU 8192
#define NNZ_RGI 200000
#define SPLIT 16
#define MCH (MN / SPLIT)

// ---------------- stream/event objects (host-side, created once) -------------
static cudaStream_t s_b;
static cudaEvent_t s_e0, s_e1, s_e2;
namespace {
struct StreamInit {
    StreamInit() {
        cudaStreamCreateWithFlags(&s_b, cudaStreamNonBlocking);
        cudaEventCreateWithFlags(&s_e0, cudaEventDisableTiming);
        cudaEventCreateWithFlags(&s_e1, cudaEventDisableTiming);
        cudaEventCreateWithFlags(&s_e2, cudaEventDisableTiming);
    }
};
StreamInit s_init_;
}  // namespace

// ---------------- scratch (device globals) ----------------------------------
__device__ float  g_rui_ei[(size_t)UN * FN];
__device__ float  g_rgu_t [(size_t)UN * FN];
__device__ float  g_rgi_t [(size_t)IN_ * FN];
__device__ float  g_rui_t [(size_t)IN_ * FN];
__device__ float  g_rgi_ei[(size_t)GN * FN];
__device__ float  g_rgu_eu[(size_t)GN * FN];
__device__ float  g_att_g [(size_t)GN * FN];
__device__ float  g_attitem[(size_t)IN_ * FN];
__device__ float  g_acc[(size_t)IN_ * FN];      // attn2 atomic accumulator
__device__ float  g_sum[MN];
__device__ __half g_members_h[(size_t)MN * FN];
__device__ __half g_item_h[(size_t)IN_ * FN];
__device__ __half g_bmat[(size_t)MN * FN];
__device__ __half g_S[(size_t)MN * IN_];
__device__ __half g_Wu_h[5 * FN * FN];
__device__ __half g_Wi_h[5 * FN * FN];
__device__ __half g_Wg_h[5 * FN * FN];

// ---------------- helpers ----------------------------------------------------
__device__ __forceinline__ uint32_t s2u(const void* p) {
    uint32_t a;
    asm("{ .reg .u64 t; cvta.to.shared.u64 t, %1; cvt.u32.u64 %0, t; }"
        : "=r"(a) : "l"(p));
    return a;
}
__device__ __forceinline__ void cpa16(uint32_t s, const void* g) {
    asm volatile("cp.async.cg.shared.global [%0], [%1], 16;"
                 :: "r"(s), "l"(g) : "memory");
}
__device__ __forceinline__ void cp_commit() {
    asm volatile("cp.async.commit_group;" ::: "memory");
}
template <int N>
__device__ __forceinline__ void cp_wait() {
    asm volatile("cp.async.wait_group %0;" :: "n"(N) : "memory");
}
__device__ __forceinline__ void ldsm4(uint32_t* r, uint32_t addr) {
    asm volatile("ldmatrix.sync.aligned.m8n8.x4.shared.b16 {%0,%1,%2,%3}, [%4];"
                 : "=r"(r[0]), "=r"(r[1]), "=r"(r[2]), "=r"(r[3]) : "r"(addr));
}
__device__ __forceinline__ void ldsm4t(uint32_t* r, uint32_t addr) {
    asm volatile("ldmatrix.sync.aligned.m8n8.x4.trans.shared.b16 {%0,%1,%2,%3}, [%4];"
                 : "=r"(r[0]), "=r"(r[1]), "=r"(r[2]), "=r"(r[3]) : "r"(addr));
}
__device__ __forceinline__ void mma16(float* c, const uint32_t* a, const uint32_t* b) {
    asm volatile(
        "mma.sync.aligned.m16n8k16.row.col.f32.f16.f16.f32 "
        "{%0,%1,%2,%3},{%4,%5,%6,%7},{%8,%9},{%0,%1,%2,%3};"
        : "+f"(c[0]), "+f"(c[1]), "+f"(c[2]), "+f"(c[3])
        : "r"(a[0]), "r"(a[1]), "r"(a[2]), "r"(a[3]), "r"(b[0]), "r"(b[1]));
}
__device__ __forceinline__ void red4(float* o, float x, float y, float z, float w) {
    asm volatile("red.global.add.v4.f32 [%0], {%1,%2,%3,%4};"
                 :: "l"(o), "f"(x), "f"(y), "f"(z), "f"(w) : "memory");
}
__device__ __forceinline__ void red2(float* o, float x, float y) {
    asm volatile("red.global.add.v2.f32 [%0], {%1,%2};"
                 :: "l"(o), "f"(x), "f"(y) : "memory");
}
__device__ __forceinline__ float pexp(float x) {
    float r = 2.7557319e-6f;
    r = fmaf(r, x, 2.4801587e-5f);
    r = fmaf(r, x, 1.9841270e-4f);
    r = fmaf(r, x, 1.3888889e-3f);
    r = fmaf(r, x, 8.3333333e-3f);
    r = fmaf(r, x, 4.1666667e-2f);
    r = fmaf(r, x, 1.6666667e-1f);
    r = fmaf(r, x, 0.5f);
    r = fmaf(r, x, 1.0f);
    r = fmaf(r, x, 1.0f);
    return r;
}
__device__ __forceinline__ uint32_t h2u(__half2 h) { return *(uint32_t*)&h; }
__device__ __forceinline__ uint4 f8_to_h8(float4 v0, float4 v1) {
    uint4 o;
    o.x = h2u(__floats2half2_rn(v0.x, v0.y));
    o.y = h2u(__floats2half2_rn(v0.z, v0.w));
    o.z = h2u(__floats2half2_rn(v1.x, v1.y));
    o.w = h2u(__floats2half2_rn(v1.z, v1.w));
    return o;
}
__device__ __forceinline__ uint4 hmul8(uint4 a, uint4 b) {
    uint4 o;
    o.x = h2u(__hmul2(*(__half2*)&a.x, *(__half2*)&b.x));
    o.y = h2u(__hmul2(*(__half2*)&a.y, *(__half2*)&b.y));
    o.z = h2u(__hmul2(*(__half2*)&a.z, *(__half2*)&b.z));
    o.w = h2u(__hmul2(*(__half2*)&a.w, *(__half2*)&b.w));
    return o;
}

// =============== fat0: all fp32->fp16 conversions + member gather =============
__global__ __launch_bounds__(256) void fat0_k(
    const float* __restrict__ user, const int* __restrict__ idx,
    const float* __restrict__ item,
    const float* __restrict__ Wu, const float* __restrict__ Wi,
    const float* __restrict__ Wg) {
    int bid = blockIdx.x;
    int t = (bid & 511) * 256 + threadIdx.x;
    if (bid < 512) {                          // gather members
        int m = t >> 4, j = t & 15;
        const float* src = user + (size_t)idx[m] * FN + j * 8;
        ((uint4*)g_members_h)[t] =
            f8_to_h8(*(const float4*)src, *(const float4*)(src + 4));
    } else if (bid < 1024) {                  // item conv
        float4 v0 = ((const float4*)item)[t * 2];
        float4 v1 = ((const float4*)item)[t * 2 + 1];
        ((uint4*)g_item_h)[t] = f8_to_h8(v0, v1);
    } else {                                  // W convs: 40 CTAs each
        int g = (bid - 1024) / 40, lb = (bid - 1024) % 40;
        int u = lb * 256 + threadIdx.x;
        if (u < 10240) {
            const float* src = g == 0 ? Wu : (g == 1 ? Wi : Wg);
            __half* dst = g == 0 ? g_Wu_h : (g == 1 ? g_Wi_h : g_Wg_h);
            float4 v0 = ((const float4*)src)[u * 2];
            float4 v1 = ((const float4*)src)[u * 2 + 1];
            ((uint4*)dst)[u] = f8_to_h8(v0, v1);
        }
    }
}

// =============== GEMM1 (fp16 mma, cp.async 2-stage) + exp + staged S store ====
#define PIT 40
__global__ __launch_bounds__(256, 2) void gemm_s_k() {
    __shared__ __half SM[20480];
    __shared__ float rs[128][4];
    int bm = blockIdx.y * 128, bn = blockIdx.x * 128;
    int tid = threadIdx.x, lane = tid & 31, warp = tid >> 5;
    int wm = warp >> 2, wn = warp & 3;
    int qr = lane >> 2, qc = lane & 3;
    int q = lane >> 3, r = lane & 7;
    uint32_t base = s2u(SM);
    int row0 = tid >> 2, c80 = (tid & 3) * 8;
    int row1 = (tid + 256) >> 2, c81 = ((tid + 256) & 3) * 8;
    float acc[4][4][4];
#pragma unroll
    for (int i = 0; i < 4; i++)
#pragma unroll
        for (int j = 0; j < 4; j++)
#pragma unroll
            for (int c = 0; c < 4; c++) acc[i][j][c] = 0.f;

    {
        cpa16(base + (row0 * PIT + c80) * 2,
              g_members_h + (size_t)(bm + row0) * FN + c80);
        cpa16(base + (row1 * PIT + c81) * 2,
              g_members_h + (size_t)(bm + row1) * FN + c81);
        cpa16(base + (10240 + row0 * PIT + c80) * 2,
              g_item_h + (size_t)(bn + row0) * FN + c80);
        cpa16(base + (10240 + row1 * PIT + c81) * 2,
              g_item_h + (size_t)(bn + row1) * FN + c81);
        cp_commit();
    }
#pragma unroll
    for (int ki = 0; ki < 4; ++ki) {
        if (ki < 3) {
            int k0 = (ki + 1) * 32, st = (ki + 1) & 1;
            cpa16(base + (st * 5120 + row0 * PIT + c80) * 2,
                  g_members_h + (size_t)(bm + row0) * FN + k0 + c80);
            cpa16(base + (st * 5120 + row1 * PIT + c81) * 2,
                  g_members_h + (size_t)(bm + row1) * FN + k0 + c81);
            cpa16(base + (10240 + st * 5120 + row0 * PIT + c80) * 2,
                  g_item_h + (size_t)(bn + row0) * FN + k0 + c80);
            cpa16(base + (10240 + st * 5120 + row1 * PIT + c81) * 2,
                  g_item_h + (size_t)(bn + row1) * FN + k0 + c81);
            cp_commit();
            cp_wait<1>();
        } else {
            cp_wait<0>();
        }
        __syncthreads();
        int st = ki & 1;
        uint32_t ab = base + st * 5120 * 2;
        uint32_t bb = base + (10240 + st * 5120) * 2;
#pragma unroll
        for (int ks = 0; ks < 2; ++ks) {
            int kl = ks * 16 + (q >> 1) * 8;
            uint32_t a[4][4], b[4][2];
#pragma unroll
            for (int mi = 0; mi < 4; ++mi) {
                int arow = wm * 64 + mi * 16 + (q & 1) * 8 + r;
                ldsm4(a[mi], ab + (arow * PIT + kl) * 2);
            }
#pragma unroll
            for (int j = 0; j < 2; ++j) {
                int brow = wn * 32 + j * 16 + (q & 1) * 8 + r;
                uint32_t t[4];
                ldsm4(t, bb + (brow * PIT + kl) * 2);
                b[j * 2][0] = t[0]; b[j * 2 + 1][0] = t[1];
                b[j * 2][1] = t[2]; b[j * 2 + 1][1] = t[3];
            }
#pragma unroll
            for (int mi = 0; mi < 4; ++mi)
#pragma unroll
                for (int ni = 0; ni < 4; ++ni) mma16(acc[mi][ni], a[mi], b[ni]);
        }
        __syncthreads();
    }
    // epilogue: exp -> smem staging + row sums
#pragma unroll
    for (int mi = 0; mi < 4; ++mi) {
        int r0 = wm * 64 + mi * 16 + qr;
        float s0 = 0.f, s1 = 0.f;
#pragma unroll
        for (int ni = 0; ni < 4; ++ni) {
            int lc = wn * 32 + ni * 8 + qc * 2;
            float e0 = pexp(acc[mi][ni][0]), e1 = pexp(acc[mi][ni][1]);
            float e2 = pexp(acc[mi][ni][2]), e3 = pexp(acc[mi][ni][3]);
            *(__half2*)&SM[r0 * 136 + lc] = __floats2half2_rn(e0, e1);
            *(__half2*)&SM[(r0 + 8) * 136 + lc] = __floats2half2_rn(e2, e3);
            s0 += e0 + e1; s1 += e2 + e3;
        }
        s0 += __shfl_xor_sync(0xffffffffu, s0, 1);
        s0 += __shfl_xor_sync(0xffffffffu, s0, 2);
        s1 += __shfl_xor_sync(0xffffffffu, s1, 1);
        s1 += __shfl_xor_sync(0xffffffffu, s1, 2);
        if (qc == 0) { rs[r0][wn] = s0; rs[r0 + 8][wn] = s1; }
    }
    __syncthreads();
    // coalesced copy-out: 2048 chunks of 16B, 8 per thread
#pragma unroll
    for (int it = 0; it < 8; ++it) {
        int ch = tid + it * 256;
        int row = ch >> 4, c8 = (ch & 15) * 8;
        uint4 v = *(const uint4*)&SM[row * 136 + c8];
        *(uint4*)(g_S + (size_t)(bm + row) * IN_ + bn + c8) = v;
    }
    if (tid < 128) {
        float s = rs[tid][0] + rs[tid][1] + rs[tid][2] + rs[tid][3];
        atomicAdd(&g_sum[bm + tid], s);
    }
}

__global__ void inv_bmat_k() {
    int t = blockIdx.x * blockDim.x + threadIdx.x;
    if (t >= MN * 16) return;
    int m = t >> 4;
    float sc = 4096.0f / g_sum[m];
    uint4 v = ((const uint4*)g_members_h)[t];
    __half2 s2 = __float2half2_rn(sc);
    uint4 o;
    o.x = h2u(__hmul2(*(__half2*)&v.x, s2));
    o.y = h2u(__hmul2(*(__half2*)&v.y, s2));
    o.z = h2u(__hmul2(*(__half2*)&v.z, s2));
    o.w = h2u(__hmul2(*(__half2*)&v.w, s2));
    ((uint4*)g_bmat)[t] = o;
}

// =============== GEMM2 (fp16 mma, split-K, cp.async 2-stage, red2) ============
#define PIT2 136
__global__ __launch_bounds__(256, 2) void attn2_k() {
    __shared__ __half Ssm[2][32 * PIT2];
    __shared__ __half Bsm[2][32 * PIT2];
    int bi = blockIdx.x * 128;
    int ms = blockIdx.y * MCH;
    int tid = threadIdx.x, lane = tid & 31, warp = tid >> 5;
    int wm = warp >> 2, wn = warp & 3;
    int qr = lane >> 2, qc = lane & 3;
    int q = lane >> 3, r = lane & 7;
    uint32_t sbase = s2u(Ssm), bbase = s2u(Bsm);
    int smm0 = tid >> 4, sc80 = (tid & 15) * 8;
    int smm1 = (tid + 256) >> 4, sc81 = ((tid + 256) & 15) * 8;
    float acc[4][4][4];
#pragma unroll
    for (int i = 0; i < 4; i++)
#pragma unroll
        for (int j = 0; j < 4; j++)
#pragma unroll
            for (int c = 0; c < 4; c++) acc[i][j][c] = 0.f;

    const int NIT = MCH / 32;
    {
        cpa16(sbase + (smm0 * PIT2 + sc80) * 2,
              g_S + (size_t)(ms + smm0) * IN_ + bi + sc80);
        cpa16(sbase + (smm1 * PIT2 + sc81) * 2,
              g_S + (size_t)(ms + smm1) * IN_ + bi + sc81);
        cpa16(bbase + (smm0 * PIT2 + sc80) * 2,
              g_bmat + (size_t)(ms + smm0) * FN + sc80);
        cpa16(bbase + (smm1 * PIT2 + sc81) * 2,
              g_bmat + (size_t)(ms + smm1) * FN + sc81);
        cp_commit();
    }
    for (int j = 0; j < NIT; ++j) {
        if (j + 1 < NIT) {
            int m0 = ms + (j + 1) * 32, st = (j + 1) & 1;
            cpa16(sbase + (st * 32 * PIT2 + smm0 * PIT2 + sc80) * 2,
                  g_S + (size_t)(m0 + smm0) * IN_ + bi + sc80);
            cpa16(sbase + (st * 32 * PIT2 + smm1 * PIT2 + sc81) * 2,
                  g_S + (size_t)(m0 + smm1) * IN_ + bi + sc81);
            cpa16(bbase + (st * 32 * PIT2 + smm0 * PIT2 + sc80) * 2,
                  g_bmat + (size_t)(m0 + smm0) * FN + sc80);
            cpa16(bbase + (st * 32 * PIT2 + smm1 * PIT2 + sc81) * 2,
                  g_bmat + (size_t)(m0 + smm1) * FN + sc81);
            cp_commit();
            cp_wait<1>();
        } else {
            cp_wait<0>();
        }
        __syncthreads();
        int st = j & 1;
        uint32_t sb = sbase + st * 32 * PIT2 * 2;
        uint32_t bb = bbase + st * 32 * PIT2 * 2;
#pragma unroll
        for (int ks = 0; ks < 2; ++ks) {
            int k0l = ks * 16;
            uint32_t a[4][4], b[4][2];
#pragma unroll
            for (int mi = 0; mi < 4; ++mi) {
                int row = k0l + (q >> 1) * 8 + r;
                int col = wm * 64 + mi * 16 + (q & 1) * 8;
                ldsm4t(a[mi], sb + (row * PIT2 + col) * 2);
            }
#pragma unroll
            for (int jn = 0; jn < 2; ++jn) {
                int row = k0l + (q & 1) * 8 + r;
                int col = wn * 32 + jn * 16 + (q >> 1) * 8;
                uint32_t t[4];
                ldsm4t(t, bb + (row * PIT2 + col) * 2);
                b[jn * 2][0] = t[0]; b[jn * 2][1] = t[1];
                b[jn * 2 + 1][0] = t[2]; b[jn * 2 + 1][1] = t[3];
            }
#pragma unroll
            for (int mi = 0; mi < 4; ++mi)
#pragma unroll
                for (int ni = 0; ni < 4; ++ni) mma16(acc[mi][ni], a[mi], b[ni]);
        }
        __syncthreads();
    }
#pragma unroll
    for (int mi = 0; mi < 4; ++mi) {
        int r0 = wm * 64 + mi * 16 + qr;
#pragma unroll
        for (int ni = 0; ni < 4; ++ni) {
            int col = wn * 32 + ni * 8 + qc * 2;
            red2(g_acc + (size_t)(bi + r0) * FN + col, acc[mi][ni][0], acc[mi][ni][1]);
            red2(g_acc + (size_t)(bi + r0 + 8) * FN + col, acc[mi][ni][2], acc[mi][ni][3]);
        }
    }
}

// =============== attitem = g_acc * item * 2^-12 ================================
__global__ void attn2_reduce_k(const float* __restrict__ item) {
    int t = blockIdx.x * blockDim.x + threadIdx.x;
    if (t >= IN_ * FN / 4) return;
    float4 s = ((const float4*)g_acc)[t];
    float4 e = ((const float4*)item)[t];
    const float c = 0.000244140625f;  // 2^-12
    s.x *= e.x * c; s.y *= e.y * c; s.z *= e.z * c; s.w *= e.w * c;
    ((float4*)g_attitem)[t] = s;
}

// =============== dual COO scatter ==============================================
__global__ void spmm_dual_k(const int* __restrict__ rows,
                            const int* __restrict__ cols,
                            const float* __restrict__ vals,
                            const float* __restrict__ X1, float* __restrict__ out1,
                            const float* __restrict__ X2, float* __restrict__ out2,
                            int nnz) {
    int w = (int)((blockIdx.x * 256u + threadIdx.x) >> 5);
    if (w >= nnz) return;
    int lane = threadIdx.x & 31;
    int r = rows[w], c = cols[w];
    float v = vals[w];
    float4 x1 = ((const float4*)(X1 + (size_t)c * FN))[lane];
    float4 x2 = ((const float4*)(X2 + (size_t)r * FN))[lane];
    red4(out1 + (size_t)r * FN + lane * 4, v * x1.x, v * x1.y, v * x1.z, v * x1.w);
    red4(out2 + (size_t)c * FN + lane * 4, v * x2.x, v * x2.y, v * x2.z, v * x2.w);
}

// =============== single COO scatter (att_g) ====================================
__global__ void spmm_k(const int* __restrict__ rows, const int* __restrict__ cols,
                       const float* __restrict__ vals, const float* __restrict__ X,
                       float* __restrict__ out, int nnz) {
    int w = (int)((blockIdx.x * 256u + threadIdx.x) >> 5);
    if (w >= nnz) return;
    int lane = threadIdx.x & 31;
    int r = rows[w], c = cols[w];
    float v = vals[w];
    float4 x = ((const float4*)(X + (size_t)c * FN))[lane];
    float* o = out + (size_t)r * FN + lane * 4;
    red4(o, v * x.x, v * x.y, v * x.z, v * x.w);
}

// =============== fused lin5 (fp16 mma, Bs cp.async 2-stage) ====================
// MODE 0 (user/item): xs = [e, a, a*e, b*e, b];  MODE 1 (group): [e, a, b*e, a*e, c]
template <int MODE>
__global__ __launch_bounds__(256, 2) void lin5_k(
    const float* __restrict__ E, const float* __restrict__ A,
    const float* __restrict__ B, const float* __restrict__ C4,
    const __half* __restrict__ Wh, const float* __restrict__ bias,
    float* __restrict__ out, int Md) {
    __shared__ __half raw[3][128 * 32];
    __shared__ __half As[128 * PIT];
    __shared__ __half Bs[2][128 * PIT];
    __shared__ float rs[128][4];
    __shared__ float bsum[128];
    int tid = threadIdx.x, lane = tid & 31, warp = tid >> 5;
    int wm = warp >> 2, wn = warp & 3;
    int qr = lane >> 2, qc = lane & 3;
    int q = lane >> 3, r = lane & 7;
    uint32_t abase = s2u(As), bbase = s2u(Bs);
    int bm = blockIdx.x * 128;
    int brow0 = tid >> 2, bc80 = (tid & 3) * 8;
    int brow1 = (tid + 256) >> 2, bc81 = ((tid + 256) & 3) * 8;
    if (tid < 128)
        bsum[tid] = bias[tid] + bias[128 + tid] + bias[256 + tid] +
                    bias[384 + tid] + bias[512 + tid];
    float acc[4][4][4];
#pragma unroll
    for (int i = 0; i < 4; i++)
#pragma unroll
        for (int j = 0; j < 4; j++)
#pragma unroll
            for (int c = 0; c < 4; c++) acc[i][j][c] = 0.f;

    {
        cpa16(bbase + (brow0 * PIT + bc80) * 2, Wh + (size_t)brow0 * FN + bc80);
        cpa16(bbase + (brow1 * PIT + bc81) * 2, Wh + (size_t)brow1 * FN + bc81);
        cp_commit();
    }
    for (int s = 0; s < 20; ++s) {
        int fbi = s / 5, kblk = s % 5, fb = fbi * 32;
        if (kblk == 0) {
#pragma unroll
            for (int it = 0; it < 6; ++it) {
                int ch = tid + it * 256;
                int tilei = ch / 512, rem = ch & 511;
                int row = rem >> 2, c8 = (rem & 3) * 8;
                int m = bm + row;
                float4 v0 = {0.f, 0.f, 0.f, 0.f}, v1 = {0.f, 0.f, 0.f, 0.f};
                if (m < Md) {
                    const float* src = tilei == 0 ? E : (tilei == 1 ? A : B);
                    size_t off = (size_t)m * FN + fb + c8;
                    v0 = *(const float4*)(src + off);
                    v1 = *(const float4*)(src + off + 4);
                }
                *(uint4*)&raw[tilei][row * 32 + c8] = f8_to_h8(v0, v1);
            }
            __syncthreads();
        }
#pragma unroll
        for (int it = 0; it < 2; ++it) {
            int ch = tid + it * 256;
            int row = ch >> 2, c8 = (ch & 3) * 8;
            uint4 o;
            if (kblk == 0) o = *(const uint4*)&raw[0][row * 32 + c8];
            else if (kblk == 1) o = *(const uint4*)&raw[1][row * 32 + c8];
            else if (kblk == 2)
                o = hmul8(*(const uint4*)&raw[MODE == 0 ? 1 : 2][row * 32 + c8],
                          *(const uint4*)&raw[0][row * 32 + c8]);
            else if (kblk == 3)
                o = hmul8(*(const uint4*)&raw[MODE == 0 ? 2 : 1][row * 32 + c8],
                          *(const uint4*)&raw[0][row * 32 + c8]);
            else {
                if (MODE == 0) o = *(const uint4*)&raw[2][row * 32 + c8];
                else {
                    int m = bm + row;
                    float4 v0 = {0.f, 0.f, 0.f, 0.f}, v1 = v0;
                    if (m < Md) {
                        size_t off = (size_t)m * FN + fb + c8;
                        v0 = *(const float4*)(C4 + off);
                        v1 = *(const float4*)(C4 + off + 4);
                    }
                    o = f8_to_h8(v0, v1);
                }
            }
            *(uint4*)&As[row * PIT + c8] = o;
        }
        if (s < 19) {
            int nk = (s + 1) % 5, nfb = ((s + 1) / 5) * 32, st = (s + 1) & 1;
            cpa16(bbase + (st * 128 * PIT + brow0 * PIT + bc80) * 2,
                  Wh + (size_t)nk * 16384 + (size_t)brow0 * FN + nfb + bc80);
            cpa16(bbase + (st * 128 * PIT + brow1 * PIT + bc81) * 2,
                  Wh + (size_t)nk * 16384 + (size_t)brow1 * FN + nfb + bc81);
            cp_commit();
            cp_wait<1>();
        } else {
            cp_wait<0>();
        }
        __syncthreads();
        uint32_t bb = bbase + (s & 1) * 128 * PIT * 2;
#pragma unroll
        for (int ks = 0; ks < 2; ++ks) {
            int kl = ks * 16 + (q >> 1) * 8;
            uint32_t a[4][4], b[4][2];
#pragma unroll
            for (int mi = 0; mi < 4; ++mi) {
                int arow = wm * 64 + mi * 16 + (q & 1) * 8 + r;
                ldsm4(a[mi], abase + (arow * PIT + kl) * 2);
            }
#pragma unroll
            for (int j = 0; j < 2; ++j) {
                int brow = wn * 32 + j * 16 + (q & 1) * 8 + r;
                uint32_t t[4];
                ldsm4(t, bb + (brow * PIT + kl) * 2);
                b[j * 2][0] = t[0]; b[j * 2 + 1][0] = t[1];
                b[j * 2][1] = t[2]; b[j * 2 + 1][1] = t[3];
            }
#pragma unroll
            for (int mi = 0; mi < 4; ++mi)
#pragma unroll
                for (int ni = 0; ni < 4; ++ni) mma16(acc[mi][ni], a[mi], b[ni]);
        }
        __syncthreads();
    }
#pragma unroll
    for (int mi = 0; mi < 4; ++mi) {
        int r0 = wm * 64 + mi * 16 + qr;
        float s0 = 0.f, s1 = 0.f;
#pragma unroll
        for (int ni = 0; ni < 4; ++ni) {
            int col = wn * 32 + ni * 8 + qc * 2;
            float b0 = bsum[col], b1 = bsum[col + 1];
            float v0 = acc[mi][ni][0] + b0, v1 = acc[mi][ni][1] + b1;
            float v2 = acc[mi][ni][2] + b0, v3 = acc[mi][ni][3] + b1;
            v0 = v0 >= 0.f ? v0 : 0.01f * v0;
            v1 = v1 >= 0.f ? v1 : 0.01f * v1;
            v2 = v2 >= 0.f ? v2 : 0.01f * v2;
            v3 = v3 >= 0.f ? v3 : 0.01f * v3;
            acc[mi][ni][0] = v0; acc[mi][ni][1] = v1;
            acc[mi][ni][2] = v2; acc[mi][ni][3] = v3;
            s0 += v0 * v0 + v1 * v1;
            s1 += v2 * v2 + v3 * v3;
        }
        s0 += __shfl_xor_sync(0xffffffffu, s0, 1);
        s0 += __shfl_xor_sync(0xffffffffu, s0, 2);
        s1 += __shfl_xor_sync(0xffffffffu, s1, 1);
        s1 += __shfl_xor_sync(0xffffffffu, s1, 2);
        if (qc == 0) { rs[r0][wn] = s0; rs[r0 + 8][wn] = s1; }
    }
    __syncthreads();
#pragma unroll
    for (int mi = 0; mi < 4; ++mi) {
        int r0 = wm * 64 + mi * 16 + qr;
        float t0 = rs[r0][0] + rs[r0][1] + rs[r0][2] + rs[r0][3];
        float t1 = rs[r0 + 8][0] + rs[r0 + 8][1] + rs[r0 + 8][2] + rs[r0 + 8][3];
        float i0 = 1.0f / fmaxf(sqrtf(t0), 1e-12f);
        float i1 = 1.0f / fmaxf(sqrtf(t1), 1e-12f);
        int m0g = bm + r0, m1g = m0g + 8;
#pragma unroll
        for (int ni = 0; ni < 4; ++ni) {
            int col = wn * 32 + ni * 8 + qc * 2;
            if (m0g < Md) {
                float2 v = {acc[mi][ni][0] * i0, acc[mi][ni][1] * i0};
                *(float2*)(out + (size_t)m0g * FN + col) = v;
            }
            if (m1g < Md) {
                float2 v = {acc[mi][ni][2] * i1, acc[mi][ni][3] * i1};
                *(float2*)(out + (size_t)m1g * FN + col) = v;
            }
        }
    }
}

// =============== launch =========================================================
extern "C" void kernel_launch(void* const* d_in, const int* in_sizes, int n_in,
                              void* d_out, int out_size) {
    const float* group_emb = (const float*)d_in[0];
    const float* user_emb  = (const float*)d_in[1];
    const float* item_emb  = (const float*)d_in[2];
    const int*   member_idx = (const int*)d_in[3];
    const int*   rui_rows = (const int*)d_in[4];
    const int*   rui_cols = (const int*)d_in[5];
    const float* rui_vals = (const float*)d_in[6];
    const int*   rgu_rows = (const int*)d_in[7];
    const int*   rgu_cols = (const int*)d_in[8];
    const float* rgu_vals = (const float*)d_in[9];
    const int*   rgi_rows = (const int*)d_in[10];
    const int*   rgi_cols = (const int*)d_in[11];
    const float* rgi_vals = (const float*)d_in[12];
    const float* Wu = (const float*)d_in[13];
    const float* bu = (const float*)d_in[14];
    const float* Wi = (const float*)d_in[15];
    const float* bi = (const float*)d_in[16];
    const float* Wg = (const float*)d_in[17];
    const float* bg = (const float*)d_in[18];

    float* out = (float*)d_out;
    float* out_g = out;
    float* out_u = out + (size_t)GN * FN;
    float* out_i = out + (size_t)(GN + UN) * FN;

    void *p_rui_ei, *p_rgu_t, *p_rgi_t, *p_rui_t, *p_rgi_ei, *p_rgu_eu,
         *p_att_g, *p_attitem, *p_sum, *p_acc, *p_wu, *p_wi, *p_wg;
    cudaGetSymbolAddress(&p_rui_ei, g_rui_ei);
    cudaGetSymbolAddress(&p_rgu_t, g_rgu_t);
    cudaGetSymbolAddress(&p_rgi_t, g_rgi_t);
    cudaGetSymbolAddress(&p_rui_t, g_rui_t);
    cudaGetSymbolAddress(&p_rgi_ei, g_rgi_ei);
    cudaGetSymbolAddress(&p_rgu_eu, g_rgu_eu);
    cudaGetSymbolAddress(&p_att_g, g_att_g);
    cudaGetSymbolAddress(&p_attitem, g_attitem);
    cudaGetSymbolAddress(&p_sum, g_sum);
    cudaGetSymbolAddress(&p_acc, g_acc);
    cudaGetSymbolAddress(&p_wu, g_Wu_h);
    cudaGetSymbolAddress(&p_wi, g_Wi_h);
    cudaGetSymbolAddress(&p_wg, g_Wg_h);

    // fork at entry: chain B owns its own memsets + scatters
    cudaEventRecord(s_e0, 0);
    cudaStreamWaitEvent(s_b, s_e0, 0);
    cudaMemsetAsync(p_rui_ei, 0, sizeof(float) * (size_t)UN * FN, s_b);
    cudaMemsetAsync(p_rgu_t, 0, sizeof(float) * (size_t)UN * FN, s_b);
    cudaMemsetAsync(p_rgi_t, 0, sizeof(float) * (size_t)IN_ * FN, s_b);
    cudaMemsetAsync(p_rui_t, 0, sizeof(float) * (size_t)IN_ * FN, s_b);
    cudaMemsetAsync(p_rgi_ei, 0, sizeof(float) * (size_t)GN * FN, s_b);
    cudaMemsetAsync(p_rgu_eu, 0, sizeof(float) * (size_t)GN * FN, s_b);
    spmm_dual_k<<<(NNZ_RUI + 7) / 8, 256, 0, s_b>>>(
        rui_rows, rui_cols, rui_vals, item_emb, (float*)p_rui_ei,
        user_emb, (float*)p_rui_t, NNZ_RUI);
    spmm_dual_k<<<(NNZ_RGU + 7) / 8, 256, 0, s_b>>>(
        rgu_rows, rgu_cols, rgu_vals, user_emb, (float*)p_rgu_eu,
        group_emb, (float*)p_rgu_t, NNZ_RGU);
    spmm_dual_k<<<(NNZ_RGI + 7) / 8, 256, 0, s_b>>>(
        rgi_rows, rgi_cols, rgi_vals, item_emb, (float*)p_rgi_ei,
        group_emb, (float*)p_rgi_t, NNZ_RGI);

    // origin: small memsets + conversions, then attention chain
    cudaMemsetAsync(p_att_g, 0, sizeof(float) * (size_t)GN * FN);
    cudaMemsetAsync(p_sum, 0, sizeof(float) * MN);
    cudaMemsetAsync(p_acc, 0, sizeof(float) * (size_t)IN_ * FN);
    fat0_k<<<1144, 256>>>(user_emb, member_idx, item_emb, Wu, Wi, Wg);
    cudaEventRecord(s_e2, 0);  // weights + fp16 operands ready

    // chain B tail: lin5 user/item need weights (s_e2) + own scatters
    cudaStreamWaitEvent(s_b, s_e2, 0);
    lin5_k<0><<<(UN + 127) / 128, 256, 0, s_b>>>(
        user_emb, (const float*)p_rui_ei, (const float*)p_rgu_t, nullptr,
        (const __half*)p_wu, bu, out_u, UN);
    lin5_k<0><<<IN_ / 128, 256, 0, s_b>>>(
        item_emb, (const float*)p_rui_t, (const float*)p_rgi_t, nullptr,
        (const __half*)p_wi, bi, out_i, IN_);
    cudaEventRecord(s_e1, s_b);

    // chain A on origin stream: attention path
    gemm_s_k<<<dim3(IN_ / 128, MN / 128), 256>>>();
    inv_bmat_k<<<512, 256>>>();
    attn2_k<<<dim3(IN_ / 128, SPLIT), 256>>>();
    attn2_reduce_k<<<(IN_ * FN / 4 + 255) / 256, 256>>>(item_emb);
    spmm_k<<<(NNZ_RGI + 7) / 8, 256>>>(rgi_rows, rgi_cols, rgi_vals,
                                       (const float*)p_attitem,
                                       (float*)p_att_g, NNZ_RGI);

    // join: group lin5 needs chain B's rgi_ei / rgu_eu
    cudaStreamWaitEvent(0, s_e1, 0);
    lin5_k<1><<<GN / 128, 256>>>(group_emb, (const float*)p_rgi_ei,
                                 (const float*)p_rgu_eu, (const float*)p_att_g,
                                 (const __half*)p_wg, bg, out_g, GN);
}

// round 17
// speedup vs baseline: 1.0408x; 1.0408x over previous
#include <cuda_runtime.h>
#include <cuda_fp16.h>
#include <math.h>
#include <stdint.h>

#define GN 4096
#define UN 100000
#define IN_ 8192
#define FN 128
#define MN 8192
#define NNZ_RUI 500000
#define NNZ_RGU 8192
#define NNZ_RGI 200000
#define SPLIT 4
#define MCH (MN / SPLIT)

// ---------------- stream/event objects (host-side, created once) -------------
static cudaStream_t s_b;
static cudaEvent_t s_e0, s_e1, s_e2;
namespace {
struct StreamInit {
    StreamInit() {
        cudaStreamCreateWithFlags(&s_b, cudaStreamNonBlocking);
        cudaEventCreateWithFlags(&s_e0, cudaEventDisableTiming);
        cudaEventCreateWithFlags(&s_e1, cudaEventDisableTiming);
        cudaEventCreateWithFlags(&s_e2, cudaEventDisableTiming);
    }
};
StreamInit s_init_;
}  // namespace

// ---------------- scratch (device globals) ----------------------------------
__device__ float  g_rui_ei[(size_t)UN * FN];
__device__ float  g_rgu_t [(size_t)UN * FN];
__device__ float  g_rgi_t [(size_t)IN_ * FN];
__device__ float  g_rui_t [(size_t)IN_ * FN];
__device__ float  g_rgi_ei[(size_t)GN * FN];
__device__ float  g_rgu_eu[(size_t)GN * FN];
__device__ float  g_att_g [(size_t)GN * FN];
__device__ float  g_attitem[(size_t)IN_ * FN];
__device__ float  g_acc[(size_t)IN_ * FN];      // attn2 atomic accumulator
__device__ float  g_sum[MN];
__device__ __half g_members_h[(size_t)MN * FN];
__device__ __half g_item_h[(size_t)IN_ * FN];
__device__ __half g_bmat[(size_t)MN * FN];
__device__ __half g_S[(size_t)MN * IN_];
__device__ __half g_Wu_h[5 * FN * FN];
__device__ __half g_Wi_h[5 * FN * FN];
__device__ __half g_Wg_h[5 * FN * FN];

// ---------------- helpers ----------------------------------------------------
__device__ __forceinline__ uint32_t s2u(const void* p) {
    uint32_t a;
    asm("{ .reg .u64 t; cvta.to.shared.u64 t, %1; cvt.u32.u64 %0, t; }"
        : "=r"(a) : "l"(p));
    return a;
}
__device__ __forceinline__ void cpa16(uint32_t s, const void* g) {
    asm volatile("cp.async.cg.shared.global [%0], [%1], 16;"
                 :: "r"(s), "l"(g) : "memory");
}
__device__ __forceinline__ void cp_commit() {
    asm volatile("cp.async.commit_group;" ::: "memory");
}
template <int N>
__device__ __forceinline__ void cp_wait() {
    asm volatile("cp.async.wait_group %0;" :: "n"(N) : "memory");
}
__device__ __forceinline__ void ldsm4(uint32_t* r, uint32_t addr) {
    asm volatile("ldmatrix.sync.aligned.m8n8.x4.shared.b16 {%0,%1,%2,%3}, [%4];"
                 : "=r"(r[0]), "=r"(r[1]), "=r"(r[2]), "=r"(r[3]) : "r"(addr));
}
__device__ __forceinline__ void ldsm4t(uint32_t* r, uint32_t addr) {
    asm volatile("ldmatrix.sync.aligned.m8n8.x4.trans.shared.b16 {%0,%1,%2,%3}, [%4];"
                 : "=r"(r[0]), "=r"(r[1]), "=r"(r[2]), "=r"(r[3]) : "r"(addr));
}
__device__ __forceinline__ void mma16(float* c, const uint32_t* a, const uint32_t* b) {
    asm volatile(
        "mma.sync.aligned.m16n8k16.row.col.f32.f16.f16.f32 "
        "{%0,%1,%2,%3},{%4,%5,%6,%7},{%8,%9},{%0,%1,%2,%3};"
        : "+f"(c[0]), "+f"(c[1]), "+f"(c[2]), "+f"(c[3])
        : "r"(a[0]), "r"(a[1]), "r"(a[2]), "r"(a[3]), "r"(b[0]), "r"(b[1]));
}
__device__ __forceinline__ void red4(float* o, float x, float y, float z, float w) {
    asm volatile("red.global.add.v4.f32 [%0], {%1,%2,%3,%4};"
                 :: "l"(o), "f"(x), "f"(y), "f"(z), "f"(w) : "memory");
}
__device__ __forceinline__ void red2(float* o, float x, float y) {
    asm volatile("red.global.add.v2.f32 [%0], {%1,%2};"
                 :: "l"(o), "f"(x), "f"(y) : "memory");
}
__device__ __forceinline__ float pexp(float x) {
    float r = 2.7557319e-6f;
    r = fmaf(r, x, 2.4801587e-5f);
    r = fmaf(r, x, 1.9841270e-4f);
    r = fmaf(r, x, 1.3888889e-3f);
    r = fmaf(r, x, 8.3333333e-3f);
    r = fmaf(r, x, 4.1666667e-2f);
    r = fmaf(r, x, 1.6666667e-1f);
    r = fmaf(r, x, 0.5f);
    r = fmaf(r, x, 1.0f);
    r = fmaf(r, x, 1.0f);
    return r;
}
__device__ __forceinline__ uint32_t h2u(__half2 h) { return *(uint32_t*)&h; }
__device__ __forceinline__ uint4 f8_to_h8(float4 v0, float4 v1) {
    uint4 o;
    o.x = h2u(__floats2half2_rn(v0.x, v0.y));
    o.y = h2u(__floats2half2_rn(v0.z, v0.w));
    o.z = h2u(__floats2half2_rn(v1.x, v1.y));
    o.w = h2u(__floats2half2_rn(v1.z, v1.w));
    return o;
}
__device__ __forceinline__ uint4 hmul8(uint4 a, uint4 b) {
    uint4 o;
    o.x = h2u(__hmul2(*(__half2*)&a.x, *(__half2*)&b.x));
    o.y = h2u(__hmul2(*(__half2*)&a.y, *(__half2*)&b.y));
    o.z = h2u(__hmul2(*(__half2*)&a.z, *(__half2*)&b.z));
    o.w = h2u(__hmul2(*(__half2*)&a.w, *(__half2*)&b.w));
    return o;
}

// =============== fat0: all fp32->fp16 conversions + member gather =============
__global__ __launch_bounds__(256) void fat0_k(
    const float* __restrict__ user, const int* __restrict__ idx,
    const float* __restrict__ item,
    const float* __restrict__ Wu, const float* __restrict__ Wi,
    const float* __restrict__ Wg) {
    int bid = blockIdx.x;
    int t = (bid & 511) * 256 + threadIdx.x;
    if (bid < 512) {                          // gather members
        int m = t >> 4, j = t & 15;
        const float* src = user + (size_t)idx[m] * FN + j * 8;
        ((uint4*)g_members_h)[t] =
            f8_to_h8(*(const float4*)src, *(const float4*)(src + 4));
    } else if (bid < 1024) {                  // item conv
        float4 v0 = ((const float4*)item)[t * 2];
        float4 v1 = ((const float4*)item)[t * 2 + 1];
        ((uint4*)g_item_h)[t] = f8_to_h8(v0, v1);
    } else {                                  // W convs: 40 CTAs each
        int g = (bid - 1024) / 40, lb = (bid - 1024) % 40;
        int u = lb * 256 + threadIdx.x;
        if (u < 10240) {
            const float* src = g == 0 ? Wu : (g == 1 ? Wi : Wg);
            __half* dst = g == 0 ? g_Wu_h : (g == 1 ? g_Wi_h : g_Wg_h);
            float4 v0 = ((const float4*)src)[u * 2];
            float4 v1 = ((const float4*)src)[u * 2 + 1];
            ((uint4*)dst)[u] = f8_to_h8(v0, v1);
        }
    }
}

// =============== GEMM1 (fp16 mma, cp.async 2-stage) + exp + staged S store ====
#define PIT 40
__global__ __launch_bounds__(256, 2) void gemm_s_k() {
    __shared__ __half SM[20480];
    __shared__ float rs[128][4];
    int bm = blockIdx.y * 128, bn = blockIdx.x * 128;
    int tid = threadIdx.x, lane = tid & 31, warp = tid >> 5;
    int wm = warp >> 2, wn = warp & 3;
    int qr = lane >> 2, qc = lane & 3;
    int q = lane >> 3, r = lane & 7;
    uint32_t base = s2u(SM);
    int row0 = tid >> 2, c80 = (tid & 3) * 8;
    int row1 = (tid + 256) >> 2, c81 = ((tid + 256) & 3) * 8;
    float acc[4][4][4];
#pragma unroll
    for (int i = 0; i < 4; i++)
#pragma unroll
        for (int j = 0; j < 4; j++)
#pragma unroll
            for (int c = 0; c < 4; c++) acc[i][j][c] = 0.f;

    {
        cpa16(base + (row0 * PIT + c80) * 2,
              g_members_h + (size_t)(bm + row0) * FN + c80);
        cpa16(base + (row1 * PIT + c81) * 2,
              g_members_h + (size_t)(bm + row1) * FN + c81);
        cpa16(base + (10240 + row0 * PIT + c80) * 2,
              g_item_h + (size_t)(bn + row0) * FN + c80);
        cpa16(base + (10240 + row1 * PIT + c81) * 2,
              g_item_h + (size_t)(bn + row1) * FN + c81);
        cp_commit();
    }
#pragma unroll
    for (int ki = 0; ki < 4; ++ki) {
        if (ki < 3) {
            int k0 = (ki + 1) * 32, st = (ki + 1) & 1;
            cpa16(base + (st * 5120 + row0 * PIT + c80) * 2,
                  g_members_h + (size_t)(bm + row0) * FN + k0 + c80);
            cpa16(base + (st * 5120 + row1 * PIT + c81) * 2,
                  g_members_h + (size_t)(bm + row1) * FN + k0 + c81);
            cpa16(base + (10240 + st * 5120 + row0 * PIT + c80) * 2,
                  g_item_h + (size_t)(bn + row0) * FN + k0 + c80);
            cpa16(base + (10240 + st * 5120 + row1 * PIT + c81) * 2,
                  g_item_h + (size_t)(bn + row1) * FN + k0 + c81);
            cp_commit();
            cp_wait<1>();
        } else {
            cp_wait<0>();
        }
        __syncthreads();
        int st = ki & 1;
        uint32_t ab = base + st * 5120 * 2;
        uint32_t bb = base + (10240 + st * 5120) * 2;
#pragma unroll
        for (int ks = 0; ks < 2; ++ks) {
            int kl = ks * 16 + (q >> 1) * 8;
            uint32_t a[4][4], b[4][2];
#pragma unroll
            for (int mi = 0; mi < 4; ++mi) {
                int arow = wm * 64 + mi * 16 + (q & 1) * 8 + r;
                ldsm4(a[mi], ab + (arow * PIT + kl) * 2);
            }
#pragma unroll
            for (int j = 0; j < 2; ++j) {
                int brow = wn * 32 + j * 16 + (q & 1) * 8 + r;
                uint32_t t[4];
                ldsm4(t, bb + (brow * PIT + kl) * 2);
                b[j * 2][0] = t[0]; b[j * 2 + 1][0] = t[1];
                b[j * 2][1] = t[2]; b[j * 2 + 1][1] = t[3];
            }
#pragma unroll
            for (int mi = 0; mi < 4; ++mi)
#pragma unroll
                for (int ni = 0; ni < 4; ++ni) mma16(acc[mi][ni], a[mi], b[ni]);
        }
        __syncthreads();
    }
    // epilogue: exp -> smem staging + row sums
#pragma unroll
    for (int mi = 0; mi < 4; ++mi) {
        int r0 = wm * 64 + mi * 16 + qr;
        float s0 = 0.f, s1 = 0.f;
#pragma unroll
        for (int ni = 0; ni < 4; ++ni) {
            int lc = wn * 32 + ni * 8 + qc * 2;
            float e0 = pexp(acc[mi][ni][0]), e1 = pexp(acc[mi][ni][1]);
            float e2 = pexp(acc[mi][ni][2]), e3 = pexp(acc[mi][ni][3]);
            *(__half2*)&SM[r0 * 136 + lc] = __floats2half2_rn(e0, e1);
            *(__half2*)&SM[(r0 + 8) * 136 + lc] = __floats2half2_rn(e2, e3);
            s0 += e0 + e1; s1 += e2 + e3;
        }
        s0 += __shfl_xor_sync(0xffffffffu, s0, 1);
        s0 += __shfl_xor_sync(0xffffffffu, s0, 2);
        s1 += __shfl_xor_sync(0xffffffffu, s1, 1);
        s1 += __shfl_xor_sync(0xffffffffu, s1, 2);
        if (qc == 0) { rs[r0][wn] = s0; rs[r0 + 8][wn] = s1; }
    }
    __syncthreads();
    // coalesced copy-out: 2048 chunks of 16B, 8 per thread
#pragma unroll
    for (int it = 0; it < 8; ++it) {
        int ch = tid + it * 256;
        int row = ch >> 4, c8 = (ch & 15) * 8;
        uint4 v = *(const uint4*)&SM[row * 136 + c8];
        *(uint4*)(g_S + (size_t)(bm + row) * IN_ + bn + c8) = v;
    }
    if (tid < 128) {
        float s = rs[tid][0] + rs[tid][1] + rs[tid][2] + rs[tid][3];
        atomicAdd(&g_sum[bm + tid], s);
    }
}

__global__ void inv_bmat_k() {
    int t = blockIdx.x * blockDim.x + threadIdx.x;
    if (t >= MN * 16) return;
    int m = t >> 4;
    float sc = 4096.0f / g_sum[m];
    uint4 v = ((const uint4*)g_members_h)[t];
    __half2 s2 = __float2half2_rn(sc);
    uint4 o;
    o.x = h2u(__hmul2(*(__half2*)&v.x, s2));
    o.y = h2u(__hmul2(*(__half2*)&v.y, s2));
    o.z = h2u(__hmul2(*(__half2*)&v.z, s2));
    o.w = h2u(__hmul2(*(__half2*)&v.w, s2));
    ((uint4*)g_bmat)[t] = o;
}

// =============== GEMM2 (fp16 mma, split-K, cp.async 2-stage, red2) ============
#define PIT2 136
__global__ __launch_bounds__(256, 2) void attn2_k() {
    __shared__ __half Ssm[2][32 * PIT2];
    __shared__ __half Bsm[2][32 * PIT2];
    int bi = blockIdx.x * 128;
    int ms = blockIdx.y * MCH;
    int tid = threadIdx.x, lane = tid & 31, warp = tid >> 5;
    int wm = warp >> 2, wn = warp & 3;
    int qr = lane >> 2, qc = lane & 3;
    int q = lane >> 3, r = lane & 7;
    uint32_t sbase = s2u(Ssm), bbase = s2u(Bsm);
    int smm0 = tid >> 4, sc80 = (tid & 15) * 8;
    int smm1 = (tid + 256) >> 4, sc81 = ((tid + 256) & 15) * 8;
    float acc[4][4][4];
#pragma unroll
    for (int i = 0; i < 4; i++)
#pragma unroll
        for (int j = 0; j < 4; j++)
#pragma unroll
            for (int c = 0; c < 4; c++) acc[i][j][c] = 0.f;

    const int NIT = MCH / 32;
    {
        cpa16(sbase + (smm0 * PIT2 + sc80) * 2,
              g_S + (size_t)(ms + smm0) * IN_ + bi + sc80);
        cpa16(sbase + (smm1 * PIT2 + sc81) * 2,
              g_S + (size_t)(ms + smm1) * IN_ + bi + sc81);
        cpa16(bbase + (smm0 * PIT2 + sc80) * 2,
              g_bmat + (size_t)(ms + smm0) * FN + sc80);
        cpa16(bbase + (smm1 * PIT2 + sc81) * 2,
              g_bmat + (size_t)(ms + smm1) * FN + sc81);
        cp_commit();
    }
    for (int j = 0; j < NIT; ++j) {
        if (j + 1 < NIT) {
            int m0 = ms + (j + 1) * 32, st = (j + 1) & 1;
            cpa16(sbase + (st * 32 * PIT2 + smm0 * PIT2 + sc80) * 2,
                  g_S + (size_t)(m0 + smm0) * IN_ + bi + sc80);
            cpa16(sbase + (st * 32 * PIT2 + smm1 * PIT2 + sc81) * 2,
                  g_S + (size_t)(m0 + smm1) * IN_ + bi + sc81);
            cpa16(bbase + (st * 32 * PIT2 + smm0 * PIT2 + sc80) * 2,
                  g_bmat + (size_t)(m0 + smm0) * FN + sc80);
            cpa16(bbase + (st * 32 * PIT2 + smm1 * PIT2 + sc81) * 2,
                  g_bmat + (size_t)(m0 + smm1) * FN + sc81);
            cp_commit();
            cp_wait<1>();
        } else {
            cp_wait<0>();
        }
        __syncthreads();
        int st = j & 1;
        uint32_t sb = sbase + st * 32 * PIT2 * 2;
        uint32_t bb = bbase + st * 32 * PIT2 * 2;
#pragma unroll
        for (int ks = 0; ks < 2; ++ks) {
            int k0l = ks * 16;
            uint32_t a[4][4], b[4][2];
#pragma unroll
            for (int mi = 0; mi < 4; ++mi) {
                int row = k0l + (q >> 1) * 8 + r;
                int col = wm * 64 + mi * 16 + (q & 1) * 8;
                ldsm4t(a[mi], sb + (row * PIT2 + col) * 2);
            }
#pragma unroll
            for (int jn = 0; jn < 2; ++jn) {
                int row = k0l + (q & 1) * 8 + r;
                int col = wn * 32 + jn * 16 + (q >> 1) * 8;
                uint32_t t[4];
                ldsm4t(t, bb + (row * PIT2 + col) * 2);
                b[jn * 2][0] = t[0]; b[jn * 2][1] = t[1];
                b[jn * 2 + 1][0] = t[2]; b[jn * 2 + 1][1] = t[3];
            }
#pragma unroll
            for (int mi = 0; mi < 4; ++mi)
#pragma unroll
                for (int ni = 0; ni < 4; ++ni) mma16(acc[mi][ni], a[mi], b[ni]);
        }
        __syncthreads();
    }
#pragma unroll
    for (int mi = 0; mi < 4; ++mi) {
        int r0 = wm * 64 + mi * 16 + qr;
#pragma unroll
        for (int ni = 0; ni < 4; ++ni) {
            int col = wn * 32 + ni * 8 + qc * 2;
            red2(g_acc + (size_t)(bi + r0) * FN + col, acc[mi][ni][0], acc[mi][ni][1]);
            red2(g_acc + (size_t)(bi + r0 + 8) * FN + col, acc[mi][ni][2], acc[mi][ni][3]);
        }
    }
}

// =============== attitem = g_acc * item * 2^-12 ================================
__global__ void attn2_reduce_k(const float* __restrict__ item) {
    int t = blockIdx.x * blockDim.x + threadIdx.x;
    if (t >= IN_ * FN / 4) return;
    float4 s = ((const float4*)g_acc)[t];
    float4 e = ((const float4*)item)[t];
    const float c = 0.000244140625f;  // 2^-12
    s.x *= e.x * c; s.y *= e.y * c; s.z *= e.z * c; s.w *= e.w * c;
    ((float4*)g_attitem)[t] = s;
}

// =============== dual COO scatter ==============================================
__global__ void spmm_dual_k(const int* __restrict__ rows,
                            const int* __restrict__ cols,
                            const float* __restrict__ vals,
                            const float* __restrict__ X1, float* __restrict__ out1,
                            const float* __restrict__ X2, float* __restrict__ out2,
                            int nnz) {
    int w = (int)((blockIdx.x * 256u + threadIdx.x) >> 5);
    if (w >= nnz) return;
    int lane = threadIdx.x & 31;
    int r = rows[w], c = cols[w];
    float v = vals[w];
    float4 x1 = ((const float4*)(X1 + (size_t)c * FN))[lane];
    float4 x2 = ((const float4*)(X2 + (size_t)r * FN))[lane];
    red4(out1 + (size_t)r * FN + lane * 4, v * x1.x, v * x1.y, v * x1.z, v * x1.w);
    red4(out2 + (size_t)c * FN + lane * 4, v * x2.x, v * x2.y, v * x2.z, v * x2.w);
}

// =============== single COO scatter (att_g) ====================================
__global__ void spmm_k(const int* __restrict__ rows, const int* __restrict__ cols,
                       const float* __restrict__ vals, const float* __restrict__ X,
                       float* __restrict__ out, int nnz) {
    int w = (int)((blockIdx.x * 256u + threadIdx.x) >> 5);
    if (w >= nnz) return;
    int lane = threadIdx.x & 31;
    int r = rows[w], c = cols[w];
    float v = vals[w];
    float4 x = ((const float4*)(X + (size_t)c * FN))[lane];
    float* o = out + (size_t)r * FN + lane * 4;
    red4(o, v * x.x, v * x.y, v * x.z, v * x.w);
}

// =============== fused lin5 (fp16 mma, Bs cp.async 2-stage) ====================
// MODE 0 (user/item): xs = [e, a, a*e, b*e, b];  MODE 1 (group): [e, a, b*e, a*e, c]
template <int MODE>
__global__ __launch_bounds__(256, 2) void lin5_k(
    const float* __restrict__ E, const float* __restrict__ A,
    const float* __restrict__ B, const float* __restrict__ C4,
    const __half* __restrict__ Wh, const float* __restrict__ bias,
    float* __restrict__ out, int Md) {
    __shared__ __half raw[3][128 * 32];
    __shared__ __half As[128 * PIT];
    __shared__ __half Bs[2][128 * PIT];
    __shared__ float rs[128][4];
    __shared__ float bsum[128];
    int tid = threadIdx.x, lane = tid & 31, warp = tid >> 5;
    int wm = warp >> 2, wn = warp & 3;
    int qr = lane >> 2, qc = lane & 3;
    int q = lane >> 3, r = lane & 7;
    uint32_t abase = s2u(As), bbase = s2u(Bs);
    int bm = blockIdx.x * 128;
    int brow0 = tid >> 2, bc80 = (tid & 3) * 8;
    int brow1 = (tid + 256) >> 2, bc81 = ((tid + 256) & 3) * 8;
    if (tid < 128)
        bsum[tid] = bias[tid] + bias[128 + tid] + bias[256 + tid] +
                    bias[384 + tid] + bias[512 + tid];
    float acc[4][4][4];
#pragma unroll
    for (int i = 0; i < 4; i++)
#pragma unroll
        for (int j = 0; j < 4; j++)
#pragma unroll
            for (int c = 0; c < 4; c++) acc[i][j][c] = 0.f;

    {
        cpa16(bbase + (brow0 * PIT + bc80) * 2, Wh + (size_t)brow0 * FN + bc80);
        cpa16(bbase + (brow1 * PIT + bc81) * 2, Wh + (size_t)brow1 * FN + bc81);
        cp_commit();
    }
    for (int s = 0; s < 20; ++s) {
        int fbi = s / 5, kblk = s % 5, fb = fbi * 32;
        if (kblk == 0) {
#pragma unroll
            for (int it = 0; it < 6; ++it) {
                int ch = tid + it * 256;
                int tilei = ch / 512, rem = ch & 511;
                int row = rem >> 2, c8 = (rem & 3) * 8;
                int m = bm + row;
                float4 v0 = {0.f, 0.f, 0.f, 0.f}, v1 = {0.f, 0.f, 0.f, 0.f};
                if (m < Md) {
                    const float* src = tilei == 0 ? E : (tilei == 1 ? A : B);
                    size_t off = (size_t)m * FN + fb + c8;
                    v0 = *(const float4*)(src + off);
                    v1 = *(const float4*)(src + off + 4);
                }
                *(uint4*)&raw[tilei][row * 32 + c8] = f8_to_h8(v0, v1);
            }
            __syncthreads();
        }
#pragma unroll
        for (int it = 0; it < 2; ++it) {
            int ch = tid + it * 256;
            int row = ch >> 2, c8 = (ch & 3) * 8;
            uint4 o;
            if (kblk == 0) o = *(const uint4*)&raw[0][row * 32 + c8];
            else if (kblk == 1) o = *(const uint4*)&raw[1][row * 32 + c8];
            else if (kblk == 2)
                o = hmul8(*(const uint4*)&raw[MODE == 0 ? 1 : 2][row * 32 + c8],
                          *(const uint4*)&raw[0][row * 32 + c8]);
            else if (kblk == 3)
                o = hmul8(*(const uint4*)&raw[MODE == 0 ? 2 : 1][row * 32 + c8],
                          *(const uint4*)&raw[0][row * 32 + c8]);
            else {
                if (MODE == 0) o = *(const uint4*)&raw[2][row * 32 + c8];
                else {
                    int m = bm + row;
                    float4 v0 = {0.f, 0.f, 0.f, 0.f}, v1 = v0;
                    if (m < Md) {
                        size_t off = (size_t)m * FN + fb + c8;
                        v0 = *(const float4*)(C4 + off);
                        v1 = *(const float4*)(C4 + off + 4);
                    }
                    o = f8_to_h8(v0, v1);
                }
            }
            *(uint4*)&As[row * PIT + c8] = o;
        }
        if (s < 19) {
            int nk = (s + 1) % 5, nfb = ((s + 1) / 5) * 32, st = (s + 1) & 1;
            cpa16(bbase + (st * 128 * PIT + brow0 * PIT + bc80) * 2,
                  Wh + (size_t)nk * 16384 + (size_t)brow0 * FN + nfb + bc80);
            cpa16(bbase + (st * 128 * PIT + brow1 * PIT + bc81) * 2,
                  Wh + (size_t)nk * 16384 + (size_t)brow1 * FN + nfb + bc81);
            cp_commit();
            cp_wait<1>();
        } else {
            cp_wait<0>();
        }
        __syncthreads();
        uint32_t bb = bbase + (s & 1) * 128 * PIT * 2;
#pragma unroll
        for (int ks = 0; ks < 2; ++ks) {
            int kl = ks * 16 + (q >> 1) * 8;
            uint32_t a[4][4], b[4][2];
#pragma unroll
            for (int mi = 0; mi < 4; ++mi) {
                int arow = wm * 64 + mi * 16 + (q & 1) * 8 + r;
                ldsm4(a[mi], abase + (arow * PIT + kl) * 2);
            }
#pragma unroll
            for (int j = 0; j < 2; ++j) {
                int brow = wn * 32 + j * 16 + (q & 1) * 8 + r;
                uint32_t t[4];
                ldsm4(t, bb + (brow * PIT + kl) * 2);
                b[j * 2][0] = t[0]; b[j * 2 + 1][0] = t[1];
                b[j * 2][1] = t[2]; b[j * 2 + 1][1] = t[3];
            }
#pragma unroll
            for (int mi = 0; mi < 4; ++mi)
#pragma unroll
                for (int ni = 0; ni < 4; ++ni) mma16(acc[mi][ni], a[mi], b[ni]);
        }
        __syncthreads();
    }
#pragma unroll
    for (int mi = 0; mi < 4; ++mi) {
        int r0 = wm * 64 + mi * 16 + qr;
        float s0 = 0.f, s1 = 0.f;
#pragma unroll
        for (int ni = 0; ni < 4; ++ni) {
            int col = wn * 32 + ni * 8 + qc * 2;
            float b0 = bsum[col], b1 = bsum[col + 1];
            float v0 = acc[mi][ni][0] + b0, v1 = acc[mi][ni][1] + b1;
            float v2 = acc[mi][ni][2] + b0, v3 = acc[mi][ni][3] + b1;
            v0 = v0 >= 0.f ? v0 : 0.01f * v0;
            v1 = v1 >= 0.f ? v1 : 0.01f * v1;
            v2 = v2 >= 0.f ? v2 : 0.01f * v2;
            v3 = v3 >= 0.f ? v3 : 0.01f * v3;
            acc[mi][ni][0] = v0; acc[mi][ni][1] = v1;
            acc[mi][ni][2] = v2; acc[mi][ni][3] = v3;
            s0 += v0 * v0 + v1 * v1;
            s1 += v2 * v2 + v3 * v3;
        }
        s0 += __shfl_xor_sync(0xffffffffu, s0, 1);
        s0 += __shfl_xor_sync(0xffffffffu, s0, 2);
        s1 += __shfl_xor_sync(0xffffffffu, s1, 1);
        s1 += __shfl_xor_sync(0xffffffffu, s1, 2);
        if (qc == 0) { rs[r0][wn] = s0; rs[r0 + 8][wn] = s1; }
    }
    __syncthreads();
#pragma unroll
    for (int mi = 0; mi < 4; ++mi) {
        int r0 = wm * 64 + mi * 16 + qr;
        float t0 = rs[r0][0] + rs[r0][1] + rs[r0][2] + rs[r0][3];
        float t1 = rs[r0 + 8][0] + rs[r0 + 8][1] + rs[r0 + 8][2] + rs[r0 + 8][3];
        float i0 = 1.0f / fmaxf(sqrtf(t0), 1e-12f);
        float i1 = 1.0f / fmaxf(sqrtf(t1), 1e-12f);
        int m0g = bm + r0, m1g = m0g + 8;
#pragma unroll
        for (int ni = 0; ni < 4; ++ni) {
            int col = wn * 32 + ni * 8 + qc * 2;
            if (m0g < Md) {
                float2 v = {acc[mi][ni][0] * i0, acc[mi][ni][1] * i0};
                *(float2*)(out + (size_t)m0g * FN + col) = v;
            }
            if (m1g < Md) {
                float2 v = {acc[mi][ni][2] * i1, acc[mi][ni][3] * i1};
                *(float2*)(out + (size_t)m1g * FN + col) = v;
            }
        }
    }
}

// =============== launch =========================================================
extern "C" void kernel_launch(void* const* d_in, const int* in_sizes, int n_in,
                              void* d_out, int out_size) {
    const float* group_emb = (const float*)d_in[0];
    const float* user_emb  = (const float*)d_in[1];
    const float* item_emb  = (const float*)d_in[2];
    const int*   member_idx = (const int*)d_in[3];
    const int*   rui_rows = (const int*)d_in[4];
    const int*   rui_cols = (const int*)d_in[5];
    const float* rui_vals = (const float*)d_in[6];
    const int*   rgu_rows = (const int*)d_in[7];
    const int*   rgu_cols = (const int*)d_in[8];
    const float* rgu_vals = (const float*)d_in[9];
    const int*   rgi_rows = (const int*)d_in[10];
    const int*   rgi_cols = (const int*)d_in[11];
    const float* rgi_vals = (const float*)d_in[12];
    const float* Wu = (const float*)d_in[13];
    const float* bu = (const float*)d_in[14];
    const float* Wi = (const float*)d_in[15];
    const float* bi = (const float*)d_in[16];
    const float* Wg = (const float*)d_in[17];
    const float* bg = (const float*)d_in[18];

    float* out = (float*)d_out;
    float* out_g = out;
    float* out_u = out + (size_t)GN * FN;
    float* out_i = out + (size_t)(GN + UN) * FN;

    void *p_rui_ei, *p_rgu_t, *p_rgi_t, *p_rui_t, *p_rgi_ei, *p_rgu_eu,
         *p_att_g, *p_attitem, *p_sum, *p_acc, *p_wu, *p_wi, *p_wg;
    cudaGetSymbolAddress(&p_rui_ei, g_rui_ei);
    cudaGetSymbolAddress(&p_rgu_t, g_rgu_t);
    cudaGetSymbolAddress(&p_rgi_t, g_rgi_t);
    cudaGetSymbolAddress(&p_rui_t, g_rui_t);
    cudaGetSymbolAddress(&p_rgi_ei, g_rgi_ei);
    cudaGetSymbolAddress(&p_rgu_eu, g_rgu_eu);
    cudaGetSymbolAddress(&p_att_g, g_att_g);
    cudaGetSymbolAddress(&p_attitem, g_attitem);
    cudaGetSymbolAddress(&p_sum, g_sum);
    cudaGetSymbolAddress(&p_acc, g_acc);
    cudaGetSymbolAddress(&p_wu, g_Wu_h);
    cudaGetSymbolAddress(&p_wi, g_Wi_h);
    cudaGetSymbolAddress(&p_wg, g_Wg_h);

    // fork at entry: chain B owns its own memsets + scatters
    cudaEventRecord(s_e0, 0);
    cudaStreamWaitEvent(s_b, s_e0, 0);
    cudaMemsetAsync(p_rui_ei, 0, sizeof(float) * (size_t)UN * FN, s_b);
    cudaMemsetAsync(p_rgu_t, 0, sizeof(float) * (size_t)UN * FN, s_b);
    cudaMemsetAsync(p_rgi_t, 0, sizeof(float) * (size_t)IN_ * FN, s_b);
    cudaMemsetAsync(p_rui_t, 0, sizeof(float) * (size_t)IN_ * FN, s_b);
    cudaMemsetAsync(p_rgi_ei, 0, sizeof(float) * (size_t)GN * FN, s_b);
    cudaMemsetAsync(p_rgu_eu, 0, sizeof(float) * (size_t)GN * FN, s_b);
    spmm_dual_k<<<(NNZ_RUI + 7) / 8, 256, 0, s_b>>>(
        rui_rows, rui_cols, rui_vals, item_emb, (float*)p_rui_ei,
        user_emb, (float*)p_rui_t, NNZ_RUI);
    spmm_dual_k<<<(NNZ_RGU + 7) / 8, 256, 0, s_b>>>(
        rgu_rows, rgu_cols, rgu_vals, user_emb, (float*)p_rgu_eu,
        group_emb, (float*)p_rgu_t, NNZ_RGU);
    spmm_dual_k<<<(NNZ_RGI + 7) / 8, 256, 0, s_b>>>(
        rgi_rows, rgi_cols, rgi_vals, item_emb, (float*)p_rgi_ei,
        group_emb, (float*)p_rgi_t, NNZ_RGI);

    // origin: small memsets + conversions, then attention chain
    cudaMemsetAsync(p_att_g, 0, sizeof(float) * (size_t)GN * FN);
    cudaMemsetAsync(p_sum, 0, sizeof(float) * MN);
    cudaMemsetAsync(p_acc, 0, sizeof(float) * (size_t)IN_ * FN);
    fat0_k<<<1144, 256>>>(user_emb, member_idx, item_emb, Wu, Wi, Wg);
    cudaEventRecord(s_e2, 0);  // weights + fp16 operands ready

    // chain B tail: lin5 user/item need weights (s_e2) + own scatters
    cudaStreamWaitEvent(s_b, s_e2, 0);
    lin5_k<0><<<(UN + 127) / 128, 256, 0, s_b>>>(
        user_emb, (const float*)p_rui_ei, (const float*)p_rgu_t, nullptr,
        (const __half*)p_wu, bu, out_u, UN);
    lin5_k<0><<<IN_ / 128, 256, 0, s_b>>>(
        item_emb, (const float*)p_rui_t, (const float*)p_rgi_t, nullptr,
        (const __half*)p_wi, bi, out_i, IN_);
    cudaEventRecord(s_e1, s_b);

    // chain A on origin stream: attention path
    gemm_s_k<<<dim3(IN_ / 128, MN / 128), 256>>>();
    inv_bmat_k<<<512, 256>>>();
    attn2_k<<<dim3(IN_ / 128, SPLIT), 256>>>();
    attn2_reduce_k<<<(IN_ * FN / 4 + 255) / 256, 256>>>(item_emb);
    spmm_k<<<(NNZ_RGI + 7) / 8, 256>>>(rgi_rows, rgi_cols, rgi_vals,
                                       (const float*)p_attitem,
                                       (float*)p_att_g, NNZ_RGI);

    // join: group lin5 needs chain B's rgi_ei / rgu_eu
    cudaStreamWaitEvent(0, s_e1, 0);
    lin5_k<1><<<GN / 128, 256>>>(group_emb, (const float*)p_rgi_ei,
                                 (const float*)p_rgu_eu, (const float*)p_att_g,
                                 (const __half*)p_wg, bg, out_g, GN);
}